// round 3
// baseline (speedup 1.0000x reference)
#include <cuda_runtime.h>
#include <cuda_bf16.h>
#include <stdint.h>

// Problem constants (match reference setup_inputs)
#define TOTAL   262144        // B*N = 16*16384
#define NGROUP  1024          // NUM_GROUPS
#define GSENT   1024          // sentinel group for masked-out nodes
#define DDIM    128
#define NBLK    256           // TOTAL / 1024 chunks for stable counting sort
#define CHUNK   1024
#define LOSS_BLOCKS 2048
#define LOSS_THREADS 256

// ---------------- scratch (static __device__, no allocation) ----------------
__device__ int   d_geff[TOTAL];
__device__ int   d_rank[TOTAL];
__device__ int   d_histT[(NGROUP + 1) * NBLK];   // [g][b]
__device__ int   d_offT [(NGROUP + 1) * NBLK];   // [g][b] exclusive over b
__device__ int   d_counts[NGROUP + 1];
__device__ int   d_starts[NGROUP + 2];
__device__ int   d_order[TOTAL];
__device__ int   d_sortedG[TOTAL];
__device__ float d_partials[2 * LOSS_BLOCKS];
__device__ int   d_maskIsByte;

// ---------------- K0: detect mask serialization (bool-as-int8 vs int32) ------
__global__ void detect_mask_kernel(const unsigned* __restrict__ mask) {
    if (threadIdx.x == 0 && blockIdx.x == 0) {
        int byteMode = 0;
        for (int i = 0; i < 256; i++) {
            if (mask[i] > 1u) { byteMode = 1; break; }
        }
        d_maskIsByte = byteMode;
    }
}

// ---------------- threefry2x32 (JAX-compatible) ----------------
__device__ __forceinline__ unsigned rotl32(unsigned v, int d) {
    return (v << d) | (v >> (32 - d));
}

__device__ __forceinline__ void threefry2x32(unsigned k0, unsigned k1,
                                             unsigned& x0, unsigned& x1) {
    const unsigned ks0 = k0, ks1 = k1, ks2 = k0 ^ k1 ^ 0x1BD11BDAu;
    x0 += ks0; x1 += ks1;
#define TF_R4(a,b,c,d)                                  \
    x0 += x1; x1 = rotl32(x1, a); x1 ^= x0;             \
    x0 += x1; x1 = rotl32(x1, b); x1 ^= x0;             \
    x0 += x1; x1 = rotl32(x1, c); x1 ^= x0;             \
    x0 += x1; x1 = rotl32(x1, d); x1 ^= x0;
    TF_R4(13,15,26, 6); x0 += ks1; x1 += ks2 + 1u;
    TF_R4(17,29,16,24); x0 += ks2; x1 += ks0 + 2u;
    TF_R4(13,15,26, 6); x0 += ks0; x1 += ks1 + 3u;
    TF_R4(17,29,16,24); x0 += ks1; x1 += ks2 + 4u;
    TF_R4(13,15,26, 6); x0 += ks2; x1 += ks0 + 5u;
#undef TF_R4
}

// u[t] of jax.random.uniform(key(42), (TOTAL,)) with threefry_partitionable
// (default True in modern JAX): per-element counter = 64-bit flat index split
// into (hi, lo) cipher words; 32-bit draw = XOR-fold of both output words.
__device__ __forceinline__ float jax_uniform_at(int t) {
    unsigned x0 = 0u;              // hi32 of 64-bit index (always 0 here)
    unsigned x1 = (unsigned)t;     // lo32
    threefry2x32(0u, 42u, x0, x1); // jax.random.key(42) -> (0, 42)
    const unsigned bits = x0 ^ x1;
    return __uint_as_float((bits >> 9) | 0x3f800000u) - 1.0f;
}

// ---------------- K1: stable per-chunk rank + per-chunk histogram ----------------
// One warp per 1024-element chunk; sequential 32-wide batches keep intra-chunk order.
__global__ void rank_kernel(const int* __restrict__ groups,
                            const void* __restrict__ maskRaw) {
    __shared__ int bins[NGROUP + 1];
    const int b = blockIdx.x;
    const int lane = threadIdx.x;
    const int byteMode = d_maskIsByte;
    const int* maskW = (const int*)maskRaw;
    const unsigned char* maskB = (const unsigned char*)maskRaw;
    for (int i = lane; i <= NGROUP; i += 32) bins[i] = 0;
    __syncwarp();
    const int base = b * CHUNK;
    for (int j = 0; j < CHUNK; j += 32) {
        const int i = base + j + lane;
        const int mv = byteMode ? (int)maskB[i] : maskW[i];
        const int g = mv ? groups[i] : GSENT;
        const unsigned m = __match_any_sync(0xffffffffu, g);
        const int rankInWarp = __popc(m & ((1u << lane) - 1u));
        const int leader = __ffs(m) - 1;
        int baseBin = 0;
        if (lane == leader) baseBin = atomicAdd(&bins[g], __popc(m));
        baseBin = __shfl_sync(0xffffffffu, baseBin, leader);
        d_rank[i] = baseBin + rankInWarp;
        d_geff[i] = g;
        __syncwarp();
    }
    for (int i = lane; i <= NGROUP; i += 32) d_histT[i * NBLK + b] = bins[i];
}

// ---------------- K2: per-group scan over chunks + total counts ----------------
__global__ void colscan_kernel() {
    const int g = blockIdx.x * blockDim.x + threadIdx.x;
    if (g > NGROUP) return;
    int cum = 0;
    const int baseIdx = g * NBLK;
    for (int b = 0; b < NBLK; b++) {
        const int h = d_histT[baseIdx + b];
        d_offT[baseIdx + b] = cum;
        cum += h;
    }
    d_counts[g] = cum;
}

// ---------------- K3: exclusive scan of counts[0..1023] -> starts ----------------
__global__ void starts_kernel() {
    __shared__ int s[2][1024];
    const int t = threadIdx.x;               // blockDim = 1024
    const int v = d_counts[t];
    s[0][t] = v;
    __syncthreads();
    int src = 0;
    for (int d = 1; d < 1024; d <<= 1) {
        int x = s[src][t];
        if (t >= d) x += s[src][t - d];
        s[src ^ 1][t] = x;
        __syncthreads();
        src ^= 1;
    }
    d_starts[t] = s[src][t] - v;             // exclusive
    if (t == 1023) d_starts[NGROUP] = s[src][1023];   // = valid_total
}

// ---------------- K4: stable scatter ----------------
__global__ void scatter_kernel() {
    const int i = blockIdx.x * blockDim.x + threadIdx.x;
    if (i >= TOTAL) return;
    const int g = d_geff[i];
    const int b = i >> 10;
    const int pos = d_starts[g] + d_offT[g * NBLK + b] + d_rank[i];
    d_order[pos] = i;
    d_sortedG[pos] = g;
}

// ---------------- K5: main loss (one warp per sorted position) ----------------
__global__ void __launch_bounds__(LOSS_THREADS)
loss_kernel(const float4* __restrict__ emb) {
    const int lane = threadIdx.x & 31;
    const int warpInBlock = threadIdx.x >> 5;
    const int warpsPerBlock = LOSS_THREADS / 32;
    const int wid = blockIdx.x * warpsPerBlock + warpInBlock;
    const int nwarps = gridDim.x * warpsPerBlock;
    const int valid_total = d_starts[NGROUP];

    float lsum = 0.0f, wsum = 0.0f;

    for (int t = wid; t < TOTAL; t += nwarps) {
        const int g   = d_sortedG[t];
        const int st  = d_starts[g];
        const int cnt = d_counts[g];
        const int anchor = d_order[t];

        const int c = max(cnt, 1);
        int pl = (t - st) - 1;
        if (pl < 0) pl += c;
        const int posi = d_order[st + pl];

        // negative sample (JAX threefry-partitionable uniform)
        const float u = jax_uniform_at(t);
        const int comp = max(valid_total - cnt, 1);
        int r = (int)(u * (float)comp);
        if (r > comp - 1) r = comp - 1;
        int np_ = (r < st) ? r : r + cnt;
        if (np_ < 0) np_ = 0;
        if (np_ > TOTAL - 1) np_ = TOTAL - 1;
        const int negi = d_order[np_];

        const float4 a = __ldg(&emb[anchor * 32 + lane]);
        const float4 p = __ldg(&emb[posi   * 32 + lane]);
        const float4 q = __ldg(&emb[negi   * 32 + lane]);

        float dp = a.x * p.x + a.y * p.y + a.z * p.z + a.w * p.w;
        float dn = a.x * q.x + a.y * q.y + a.z * q.z + a.w * q.w;
        #pragma unroll
        for (int o = 16; o; o >>= 1) {
            dp += __shfl_xor_sync(0xffffffffu, dp, o);
            dn += __shfl_xor_sync(0xffffffffu, dn, o);
        }

        const float ps = dp * 10.0f;     // / TEMPERATURE (0.1)
        const float ns = dn * 10.0f;
        // logaddexp(ps, ns) - ps  ==  max(d,0) + log1p(exp(-|d|)), d = ns - ps
        const float d = ns - ps;
        const float loss = fmaxf(d, 0.0f) + log1pf(expf(-fabsf(d)));

        const bool valid = (g < NGROUP) && (cnt >= 2) && ((valid_total - cnt) > 0);
        if (valid && lane == 0) { lsum += loss; wsum += 1.0f; }
    }

    // deterministic block reduction
    __shared__ float sl[LOSS_THREADS / 32];
    __shared__ float sw[LOSS_THREADS / 32];
    if (lane == 0) { sl[warpInBlock] = lsum; sw[warpInBlock] = wsum; }
    __syncthreads();
    if (threadIdx.x == 0) {
        float L = 0.0f, W = 0.0f;
        #pragma unroll
        for (int i = 0; i < LOSS_THREADS / 32; i++) { L += sl[i]; W += sw[i]; }
        d_partials[2 * blockIdx.x]     = L;
        d_partials[2 * blockIdx.x + 1] = W;
    }
}

// ---------------- K6: deterministic finalize ----------------
__global__ void finalize_kernel(float* __restrict__ out) {
    __shared__ float sl[256];
    __shared__ float sw[256];
    float L = 0.0f, W = 0.0f;
    for (int i = threadIdx.x; i < LOSS_BLOCKS; i += 256) {
        L += d_partials[2 * i];
        W += d_partials[2 * i + 1];
    }
    sl[threadIdx.x] = L; sw[threadIdx.x] = W;
    __syncthreads();
    for (int s = 128; s > 0; s >>= 1) {
        if (threadIdx.x < s) {
            sl[threadIdx.x] += sl[threadIdx.x + s];
            sw[threadIdx.x] += sw[threadIdx.x + s];
        }
        __syncthreads();
    }
    if (threadIdx.x == 0) out[0] = sl[0] / fmaxf(sw[0], 1.0f);
}

// ---------------- launch ----------------
extern "C" void kernel_launch(void* const* d_in, const int* in_sizes, int n_in,
                              void* d_out, int out_size) {
    const float4* emb   = (const float4*)d_in[0];
    const int*    grp   = (const int*)d_in[1];
    const void*   mask  = (const void*)d_in[2];
    float*        out   = (float*)d_out;
    (void)in_sizes; (void)n_in; (void)out_size;

    detect_mask_kernel<<<1, 32>>>((const unsigned*)mask);
    rank_kernel<<<NBLK, 32>>>(grp, mask);
    colscan_kernel<<<(NGROUP + 1 + 255) / 256, 256>>>();
    starts_kernel<<<1, 1024>>>();
    scatter_kernel<<<TOTAL / 256, 256>>>();
    loss_kernel<<<LOSS_BLOCKS, LOSS_THREADS>>>(emb);
    finalize_kernel<<<1, 256>>>(out);
}

// round 4
// speedup vs baseline: 1.5212x; 1.5212x over previous
#include <cuda_runtime.h>
#include <cuda_bf16.h>
#include <stdint.h>

// Problem constants (match reference setup_inputs)
#define TOTAL   262144        // B*N = 16*16384
#define NGROUP  1024          // NUM_GROUPS
#define GSENT   1024          // sentinel group for masked-out nodes
#define NBLK    256           // TOTAL / 1024 chunks for stable counting sort
#define CHUNK   1024
#define LOSS_THREADS 256
#define LOSS_BLOCKS  2048     // 16384 warps total
#define CHUNK_T      (TOTAL / (LOSS_BLOCKS * (LOSS_THREADS / 32)))   // 16

// ---------------- scratch (static __device__, no allocation) ----------------
__device__ int   d_geff[TOTAL];
__device__ int   d_rank[TOTAL];
__device__ int   d_histT[(NGROUP + 1) * NBLK];   // [g][b]
__device__ int   d_offT [(NGROUP + 1) * NBLK];   // [g][b] exclusive over b
__device__ int   d_counts[NGROUP + 1];
__device__ int   d_starts[NGROUP + 2];
__device__ int   d_order[TOTAL];
__device__ int   d_sortedG[TOTAL];
__device__ float d_partials[2 * LOSS_BLOCKS];
__device__ int   d_maskIsByte;

// ---------------- K0: detect mask serialization (bool-as-int8 vs int32) ------
__global__ void detect_mask_kernel(const unsigned* __restrict__ mask) {
    if (threadIdx.x == 0 && blockIdx.x == 0) {
        int byteMode = 0;
        for (int i = 0; i < 256; i++) {
            if (mask[i] > 1u) { byteMode = 1; break; }
        }
        d_maskIsByte = byteMode;
    }
}

// ---------------- threefry2x32 (JAX partitionable mode) ----------------
__device__ __forceinline__ unsigned rotl32(unsigned v, int d) {
    return (v << d) | (v >> (32 - d));
}

__device__ __forceinline__ void threefry2x32(unsigned k0, unsigned k1,
                                             unsigned& x0, unsigned& x1) {
    const unsigned ks0 = k0, ks1 = k1, ks2 = k0 ^ k1 ^ 0x1BD11BDAu;
    x0 += ks0; x1 += ks1;
#define TF_R4(a,b,c,d)                                  \
    x0 += x1; x1 = rotl32(x1, a); x1 ^= x0;             \
    x0 += x1; x1 = rotl32(x1, b); x1 ^= x0;             \
    x0 += x1; x1 = rotl32(x1, c); x1 ^= x0;             \
    x0 += x1; x1 = rotl32(x1, d); x1 ^= x0;
    TF_R4(13,15,26, 6); x0 += ks1; x1 += ks2 + 1u;
    TF_R4(17,29,16,24); x0 += ks2; x1 += ks0 + 2u;
    TF_R4(13,15,26, 6); x0 += ks0; x1 += ks1 + 3u;
    TF_R4(17,29,16,24); x0 += ks1; x1 += ks2 + 4u;
    TF_R4(13,15,26, 6); x0 += ks2; x1 += ks0 + 5u;
#undef TF_R4
}

// u[t]: counter = 64-bit flat index -> (hi=0, lo=t); draw = fold(out0^out1).
__device__ __forceinline__ float jax_uniform_at(int t) {
    unsigned x0 = 0u;
    unsigned x1 = (unsigned)t;
    threefry2x32(0u, 42u, x0, x1);       // jax.random.key(42) -> (0, 42)
    const unsigned bits = x0 ^ x1;
    return __uint_as_float((bits >> 9) | 0x3f800000u) - 1.0f;
}

// ---------------- K1: stable per-chunk rank + per-chunk histogram ----------------
__global__ void rank_kernel(const int* __restrict__ groups,
                            const void* __restrict__ maskRaw) {
    __shared__ int bins[NGROUP + 1];
    const int b = blockIdx.x;
    const int lane = threadIdx.x;
    const int byteMode = d_maskIsByte;
    const int* maskW = (const int*)maskRaw;
    const unsigned char* maskB = (const unsigned char*)maskRaw;
    for (int i = lane; i <= NGROUP; i += 32) bins[i] = 0;
    __syncwarp();
    const int base = b * CHUNK;
    for (int j = 0; j < CHUNK; j += 32) {
        const int i = base + j + lane;
        const int mv = byteMode ? (int)maskB[i] : maskW[i];
        const int g = mv ? groups[i] : GSENT;
        const unsigned m = __match_any_sync(0xffffffffu, g);
        const int rankInWarp = __popc(m & ((1u << lane) - 1u));
        const int leader = __ffs(m) - 1;
        int baseBin = 0;
        if (lane == leader) baseBin = atomicAdd(&bins[g], __popc(m));
        baseBin = __shfl_sync(0xffffffffu, baseBin, leader);
        d_rank[i] = baseBin + rankInWarp;
        d_geff[i] = g;
        __syncwarp();
    }
    for (int i = lane; i <= NGROUP; i += 32) d_histT[i * NBLK + b] = bins[i];
}

// ---------------- K2: per-group scan over chunks (one WARP per group) ----------
__global__ void colscan_kernel() {
    const int warpsPerBlock = blockDim.x >> 5;
    const int g = blockIdx.x * warpsPerBlock + (threadIdx.x >> 5);
    if (g > NGROUP) return;
    const int lane = threadIdx.x & 31;
    const int baseIdx = g * NBLK;
    int cum = 0;
    #pragma unroll
    for (int b0 = 0; b0 < NBLK; b0 += 32) {
        const int h = d_histT[baseIdx + b0 + lane];     // coalesced 128B
        int x = h;
        #pragma unroll
        for (int o = 1; o < 32; o <<= 1) {
            const int y = __shfl_up_sync(0xffffffffu, x, o);
            if (lane >= o) x += y;
        }
        d_offT[baseIdx + b0 + lane] = cum + x - h;      // exclusive
        cum += __shfl_sync(0xffffffffu, x, 31);
    }
    if (lane == 0) d_counts[g] = cum;
}

// ---------------- K3: exclusive scan of counts[0..1023] -> starts ----------------
__global__ void starts_kernel() {
    __shared__ int warpTot[32];
    const int t = threadIdx.x;               // blockDim = 1024
    const int lane = t & 31;
    const int w = t >> 5;
    const int v = d_counts[t];
    int x = v;
    #pragma unroll
    for (int o = 1; o < 32; o <<= 1) {
        const int y = __shfl_up_sync(0xffffffffu, x, o);
        if (lane >= o) x += y;
    }
    if (lane == 31) warpTot[w] = x;
    __syncthreads();
    if (w == 0) {
        int wt = warpTot[lane];
        #pragma unroll
        for (int o = 1; o < 32; o <<= 1) {
            const int y = __shfl_up_sync(0xffffffffu, wt, o);
            if (lane >= o) wt += y;
        }
        warpTot[lane] = wt;
    }
    __syncthreads();
    const int base = (w > 0) ? warpTot[w - 1] : 0;
    d_starts[t] = base + x - v;                           // exclusive
    if (t == 1023) d_starts[NGROUP] = base + x;           // = valid_total
}

// ---------------- K4: stable scatter ----------------
__global__ void scatter_kernel() {
    const int i = blockIdx.x * blockDim.x + threadIdx.x;
    if (i >= TOTAL) return;
    const int g = d_geff[i];
    const int b = i >> 10;
    const int pos = d_starts[g] + d_offT[g * NBLK + b] + d_rank[i];
    d_order[pos] = i;
    d_sortedG[pos] = g;
}

// ---------------- K5: main loss ----------------
// One warp handles CHUNK_T *consecutive* sorted positions so the anchor row of
// position t-1 can be reused as the positive row of position t (roll-by-1).
__global__ void __launch_bounds__(LOSS_THREADS)
loss_kernel(const float4* __restrict__ emb) {
    const int lane = threadIdx.x & 31;
    const int warpInBlock = threadIdx.x >> 5;
    const int warpsPerBlock = LOSS_THREADS / 32;
    const int wid = blockIdx.x * warpsPerBlock + warpInBlock;
    const int lo = wid * CHUNK_T;
    const int valid_total = d_starts[NGROUP];

    float lsum = 0.0f, wsum = 0.0f;
    float4 aPrev = make_float4(0.f, 0.f, 0.f, 0.f);
    bool havePrev = false;

    #pragma unroll 1
    for (int t = lo; t < lo + CHUNK_T; ++t) {
        const int g   = d_sortedG[t];
        const int st  = d_starts[g];
        const int cnt = d_counts[g];
        const int anchor = d_order[t];

        // negative sample (JAX threefry-partitionable uniform)
        const float u = jax_uniform_at(t);
        const int comp = max(valid_total - cnt, 1);
        int r = (int)(u * (float)comp);
        if (r > comp - 1) r = comp - 1;
        int np_ = (r < st) ? r : r + cnt;
        if (np_ < 0) np_ = 0;
        if (np_ > TOTAL - 1) np_ = TOTAL - 1;
        const int negi = d_order[np_];

        const float4 a = __ldg(&emb[anchor * 32 + lane]);
        const float4 q = __ldg(&emb[negi   * 32 + lane]);

        float4 p;
        if (t == st) {                       // wrap: partner = last in group
            const int posi = d_order[st + cnt - 1];
            p = __ldg(&emb[posi * 32 + lane]);
        } else if (havePrev) {               // partner = previous sorted pos
            p = aPrev;
        } else {                             // warp-chunk entry: one real load
            const int posi = d_order[t - 1];
            p = __ldg(&emb[posi * 32 + lane]);
        }
        aPrev = a; havePrev = true;

        float dp = a.x * p.x + a.y * p.y + a.z * p.z + a.w * p.w;
        float dn = a.x * q.x + a.y * q.y + a.z * q.z + a.w * q.w;
        #pragma unroll
        for (int o = 16; o; o >>= 1) {
            dp += __shfl_xor_sync(0xffffffffu, dp, o);
            dn += __shfl_xor_sync(0xffffffffu, dn, o);
        }

        const float ps = dp * 10.0f;     // / TEMPERATURE (0.1)
        const float ns = dn * 10.0f;
        const float d = ns - ps;         // logaddexp(ps,ns)-ps
        const float loss = fmaxf(d, 0.0f) + log1pf(expf(-fabsf(d)));

        const bool valid = (g < NGROUP) && (cnt >= 2) && ((valid_total - cnt) > 0);
        if (valid && lane == 0) { lsum += loss; wsum += 1.0f; }
    }

    // deterministic block reduction
    __shared__ float sl[LOSS_THREADS / 32];
    __shared__ float sw[LOSS_THREADS / 32];
    if (lane == 0) { sl[warpInBlock] = lsum; sw[warpInBlock] = wsum; }
    __syncthreads();
    if (threadIdx.x == 0) {
        float L = 0.0f, W = 0.0f;
        #pragma unroll
        for (int i = 0; i < LOSS_THREADS / 32; i++) { L += sl[i]; W += sw[i]; }
        d_partials[2 * blockIdx.x]     = L;
        d_partials[2 * blockIdx.x + 1] = W;
    }
}

// ---------------- K6: deterministic finalize ----------------
__global__ void finalize_kernel(float* __restrict__ out) {
    __shared__ float sl[256];
    __shared__ float sw[256];
    float L = 0.0f, W = 0.0f;
    for (int i = threadIdx.x; i < LOSS_BLOCKS; i += 256) {
        L += d_partials[2 * i];
        W += d_partials[2 * i + 1];
    }
    sl[threadIdx.x] = L; sw[threadIdx.x] = W;
    __syncthreads();
    for (int s = 128; s > 0; s >>= 1) {
        if (threadIdx.x < s) {
            sl[threadIdx.x] += sl[threadIdx.x + s];
            sw[threadIdx.x] += sw[threadIdx.x + s];
        }
        __syncthreads();
    }
    if (threadIdx.x == 0) out[0] = sl[0] / fmaxf(sw[0], 1.0f);
}

// ---------------- launch ----------------
extern "C" void kernel_launch(void* const* d_in, const int* in_sizes, int n_in,
                              void* d_out, int out_size) {
    const float4* emb   = (const float4*)d_in[0];
    const int*    grp   = (const int*)d_in[1];
    const void*   mask  = (const void*)d_in[2];
    float*        out   = (float*)d_out;
    (void)in_sizes; (void)n_in; (void)out_size;

    detect_mask_kernel<<<1, 32>>>((const unsigned*)mask);
    rank_kernel<<<NBLK, 32>>>(grp, mask);
    colscan_kernel<<<(NGROUP + 1 + 7) / 8, 256>>>();
    starts_kernel<<<1, 1024>>>();
    scatter_kernel<<<TOTAL / 256, 256>>>();
    loss_kernel<<<LOSS_BLOCKS, LOSS_THREADS>>>(emb);
    finalize_kernel<<<1, 256>>>(out);
}

// round 5
// speedup vs baseline: 1.8377x; 1.2080x over previous
#include <cuda_runtime.h>
#include <cuda_bf16.h>
#include <stdint.h>

// Problem constants (match reference setup_inputs)
#define TOTAL   262144        // B*N = 16*16384
#define NGROUP  1024          // NUM_GROUPS
#define GSENT   1024          // sentinel group for masked-out nodes
#define NBLK    256           // TOTAL / 1024 chunks for stable counting sort
#define CHUNK   1024
#define LOSS_THREADS 256
#define LOSS_BLOCKS  2048     // 16384 warps total
#define CHUNK_T      (TOTAL / (LOSS_BLOCKS * (LOSS_THREADS / 32)))   // 16

// ---------------- scratch (static __device__, no allocation) ----------------
__device__ int   d_geff[TOTAL];
__device__ int   d_rank[TOTAL];
__device__ int   d_histT[(NGROUP + 1) * NBLK];   // [g][b]
__device__ int   d_offT [(NGROUP + 1) * NBLK];   // [g][b] exclusive over b
__device__ int   d_counts[NGROUP + 1];
__device__ int   d_starts[NGROUP + 2];
__device__ int   d_order[TOTAL];
__device__ int   d_sortedG[TOTAL];
__device__ float d_partials[2 * LOSS_BLOCKS];
__device__ int   d_done;     // zero-initialized; last loss block resets to 0

// ---------------- threefry2x32 (JAX partitionable mode) ----------------
__device__ __forceinline__ unsigned rotl32(unsigned v, int d) {
    return (v << d) | (v >> (32 - d));
}

__device__ __forceinline__ void threefry2x32(unsigned k0, unsigned k1,
                                             unsigned& x0, unsigned& x1) {
    const unsigned ks0 = k0, ks1 = k1, ks2 = k0 ^ k1 ^ 0x1BD11BDAu;
    x0 += ks0; x1 += ks1;
#define TF_R4(a,b,c,d)                                  \
    x0 += x1; x1 = rotl32(x1, a); x1 ^= x0;             \
    x0 += x1; x1 = rotl32(x1, b); x1 ^= x0;             \
    x0 += x1; x1 = rotl32(x1, c); x1 ^= x0;             \
    x0 += x1; x1 = rotl32(x1, d); x1 ^= x0;
    TF_R4(13,15,26, 6); x0 += ks1; x1 += ks2 + 1u;
    TF_R4(17,29,16,24); x0 += ks2; x1 += ks0 + 2u;
    TF_R4(13,15,26, 6); x0 += ks0; x1 += ks1 + 3u;
    TF_R4(17,29,16,24); x0 += ks1; x1 += ks2 + 4u;
    TF_R4(13,15,26, 6); x0 += ks2; x1 += ks0 + 5u;
#undef TF_R4
}

// u[t]: counter = 64-bit flat index -> (hi=0, lo=t); draw = fold(out0^out1).
__device__ __forceinline__ float jax_uniform_at(int t) {
    unsigned x0 = 0u;
    unsigned x1 = (unsigned)t;
    threefry2x32(0u, 42u, x0, x1);       // jax.random.key(42) -> (0, 42)
    const unsigned bits = x0 ^ x1;
    return __uint_as_float((bits >> 9) | 0x3f800000u) - 1.0f;
}

// negative sorted-position for sorted index t
__device__ __forceinline__ int neg_pos(int t, int st, int cnt, int valid_total) {
    const float u = jax_uniform_at(t);
    const int comp = max(valid_total - cnt, 1);
    int r = (int)(u * (float)comp);
    if (r > comp - 1) r = comp - 1;
    int np_ = (r < st) ? r : r + cnt;
    if (np_ < 0) np_ = 0;
    if (np_ > TOTAL - 1) np_ = TOTAL - 1;
    return np_;
}

// ---------------- K1: stable per-chunk rank + per-chunk histogram ----------------
__global__ void rank_kernel(const int* __restrict__ groups,
                            const int* __restrict__ mask) {
    __shared__ int bins[NGROUP + 1];
    const int b = blockIdx.x;
    const int lane = threadIdx.x;
    for (int i = lane; i <= NGROUP; i += 32) bins[i] = 0;
    __syncwarp();
    const int base = b * CHUNK;
    for (int j = 0; j < CHUNK; j += 32) {
        const int i = base + j + lane;
        const int g = mask[i] ? groups[i] : GSENT;
        const unsigned m = __match_any_sync(0xffffffffu, g);
        const int rankInWarp = __popc(m & ((1u << lane) - 1u));
        const int leader = __ffs(m) - 1;
        int baseBin = 0;
        if (lane == leader) baseBin = atomicAdd(&bins[g], __popc(m));
        baseBin = __shfl_sync(0xffffffffu, baseBin, leader);
        d_rank[i] = baseBin + rankInWarp;
        d_geff[i] = g;
        __syncwarp();
    }
    for (int i = lane; i <= NGROUP; i += 32) d_histT[i * NBLK + b] = bins[i];
}

// ---------------- K2: per-group scan over chunks (one WARP per group) ----------
__global__ void colscan_kernel() {
    const int warpsPerBlock = blockDim.x >> 5;
    const int g = blockIdx.x * warpsPerBlock + (threadIdx.x >> 5);
    if (g > NGROUP) return;
    const int lane = threadIdx.x & 31;
    const int baseIdx = g * NBLK;
    int cum = 0;
    #pragma unroll
    for (int b0 = 0; b0 < NBLK; b0 += 32) {
        const int h = d_histT[baseIdx + b0 + lane];     // coalesced 128B
        int x = h;
        #pragma unroll
        for (int o = 1; o < 32; o <<= 1) {
            const int y = __shfl_up_sync(0xffffffffu, x, o);
            if (lane >= o) x += y;
        }
        d_offT[baseIdx + b0 + lane] = cum + x - h;      // exclusive
        cum += __shfl_sync(0xffffffffu, x, 31);
    }
    if (lane == 0) d_counts[g] = cum;
}

// ---------------- K3: exclusive scan of counts[0..1023] -> starts ----------------
__global__ void starts_kernel() {
    __shared__ int warpTot[32];
    const int t = threadIdx.x;               // blockDim = 1024
    const int lane = t & 31;
    const int w = t >> 5;
    const int v = d_counts[t];
    int x = v;
    #pragma unroll
    for (int o = 1; o < 32; o <<= 1) {
        const int y = __shfl_up_sync(0xffffffffu, x, o);
        if (lane >= o) x += y;
    }
    if (lane == 31) warpTot[w] = x;
    __syncthreads();
    if (w == 0) {
        int wt = warpTot[lane];
        #pragma unroll
        for (int o = 1; o < 32; o <<= 1) {
            const int y = __shfl_up_sync(0xffffffffu, wt, o);
            if (lane >= o) wt += y;
        }
        warpTot[lane] = wt;
    }
    __syncthreads();
    const int base = (w > 0) ? warpTot[w - 1] : 0;
    d_starts[t] = base + x - v;                           // exclusive
    if (t == 1023) d_starts[NGROUP] = base + x;           // = valid_total
}

// ---------------- K4: stable scatter ----------------
__global__ void scatter_kernel() {
    const int i = blockIdx.x * blockDim.x + threadIdx.x;
    if (i >= TOTAL) return;
    const int g = d_geff[i];
    const int b = i >> 10;
    const int pos = d_starts[g] + d_offT[g * NBLK + b] + d_rank[i];
    d_order[pos] = i;
    d_sortedG[pos] = g;
}

// ---------------- K5: main loss (unroll-2, roll-carry positive) ----------------
__global__ void __launch_bounds__(LOSS_THREADS)
loss_kernel(const float4* __restrict__ emb, float* __restrict__ out) {
    const int lane = threadIdx.x & 31;
    const int warpInBlock = threadIdx.x >> 5;
    const int wid = blockIdx.x * (LOSS_THREADS / 32) + warpInBlock;
    const int lo = wid * CHUNK_T;
    const int valid_total = d_starts[NGROUP];

    float lsum = 0.0f, wsum = 0.0f;
    float4 aPrev = make_float4(0.f, 0.f, 0.f, 0.f);

    #pragma unroll 1
    for (int tp = 0; tp < CHUNK_T; tp += 2) {
        const int t0 = lo + tp;
        const int t1 = t0 + 1;
        const int2 gg  = __ldg((const int2*)d_sortedG + (t0 >> 1));
        const int2 anc = __ldg((const int2*)d_order   + (t0 >> 1));
        const int st0 = d_starts[gg.x], cnt0 = d_counts[gg.x];
        const int st1 = d_starts[gg.y], cnt1 = d_counts[gg.y];

        const int negi0 = __ldg(d_order + neg_pos(t0, st0, cnt0, valid_total));
        const int negi1 = __ldg(d_order + neg_pos(t1, st1, cnt1, valid_total));

        const float4 A0 = __ldg(&emb[anc.x * 32 + lane]);
        const float4 A1 = __ldg(&emb[anc.y * 32 + lane]);
        const float4 Q0 = __ldg(&emb[negi0 * 32 + lane]);
        const float4 Q1 = __ldg(&emb[negi1 * 32 + lane]);

        float4 P0;
        if (t0 == st0) {                      // group start: wrap to last
            P0 = __ldg(&emb[__ldg(d_order + (st0 + cnt0 - 1)) * 32 + lane]);
        } else if (tp == 0) {                 // warp-chunk entry
            P0 = __ldg(&emb[__ldg(d_order + (t0 - 1)) * 32 + lane]);
        } else {
            P0 = aPrev;
        }
        float4 P1;
        if (t1 == st1) {
            P1 = __ldg(&emb[__ldg(d_order + (st1 + cnt1 - 1)) * 32 + lane]);
        } else {
            P1 = A0;
        }
        aPrev = A1;

        float dp0 = A0.x*P0.x + A0.y*P0.y + A0.z*P0.z + A0.w*P0.w;
        float dn0 = A0.x*Q0.x + A0.y*Q0.y + A0.z*Q0.z + A0.w*Q0.w;
        float dp1 = A1.x*P1.x + A1.y*P1.y + A1.z*P1.z + A1.w*P1.w;
        float dn1 = A1.x*Q1.x + A1.y*Q1.y + A1.z*Q1.z + A1.w*Q1.w;
        #pragma unroll
        for (int o = 16; o; o >>= 1) {
            dp0 += __shfl_xor_sync(0xffffffffu, dp0, o);
            dn0 += __shfl_xor_sync(0xffffffffu, dn0, o);
            dp1 += __shfl_xor_sync(0xffffffffu, dp1, o);
            dn1 += __shfl_xor_sync(0xffffffffu, dn1, o);
        }

        if (lane == 0) {
            const float d0 = (dn0 - dp0) * 10.0f;     // / TEMPERATURE
            const float d1 = (dn1 - dp1) * 10.0f;
            const float l0 = fmaxf(d0, 0.0f) + log1pf(expf(-fabsf(d0)));
            const float l1 = fmaxf(d1, 0.0f) + log1pf(expf(-fabsf(d1)));
            const bool v0 = (gg.x < NGROUP) && (cnt0 >= 2) && ((valid_total - cnt0) > 0);
            const bool v1 = (gg.y < NGROUP) && (cnt1 >= 2) && ((valid_total - cnt1) > 0);
            if (v0) { lsum += l0; wsum += 1.0f; }
            if (v1) { lsum += l1; wsum += 1.0f; }
        }
    }

    // deterministic block reduction
    __shared__ float sl[LOSS_THREADS / 32];
    __shared__ float sw[LOSS_THREADS / 32];
    __shared__ int isLast;
    if (lane == 0) { sl[warpInBlock] = lsum; sw[warpInBlock] = wsum; }
    __syncthreads();
    if (threadIdx.x == 0) {
        float L = 0.0f, W = 0.0f;
        #pragma unroll
        for (int i = 0; i < LOSS_THREADS / 32; i++) { L += sl[i]; W += sw[i]; }
        d_partials[2 * blockIdx.x]     = L;
        d_partials[2 * blockIdx.x + 1] = W;
        __threadfence();
        isLast = (atomicAdd(&d_done, 1) == LOSS_BLOCKS - 1);
    }
    __syncthreads();

    // last finishing block does the deterministic final reduction
    if (isLast) {
        __shared__ float fl[256];
        __shared__ float fw[256];
        float L = 0.0f, W = 0.0f;
        for (int i = threadIdx.x; i < LOSS_BLOCKS; i += 256) {
            L += d_partials[2 * i];
            W += d_partials[2 * i + 1];
        }
        fl[threadIdx.x] = L; fw[threadIdx.x] = W;
        __syncthreads();
        for (int s = 128; s > 0; s >>= 1) {
            if (threadIdx.x < s) {
                fl[threadIdx.x] += fl[threadIdx.x + s];
                fw[threadIdx.x] += fw[threadIdx.x + s];
            }
            __syncthreads();
        }
        if (threadIdx.x == 0) {
            out[0] = fl[0] / fmaxf(fw[0], 1.0f);
            d_done = 0;                       // reset for graph replay
        }
    }
}

// ---------------- launch ----------------
extern "C" void kernel_launch(void* const* d_in, const int* in_sizes, int n_in,
                              void* d_out, int out_size) {
    const float4* emb   = (const float4*)d_in[0];
    const int*    grp   = (const int*)d_in[1];
    const int*    mask  = (const int*)d_in[2];
    float*        out   = (float*)d_out;
    (void)in_sizes; (void)n_in; (void)out_size;

    rank_kernel<<<NBLK, 32>>>(grp, mask);
    colscan_kernel<<<(NGROUP + 1 + 7) / 8, 256>>>();
    starts_kernel<<<1, 1024>>>();
    scatter_kernel<<<TOTAL / 256, 256>>>();
    loss_kernel<<<LOSS_BLOCKS, LOSS_THREADS>>>(emb, out);
}

// round 6
// speedup vs baseline: 2.6741x; 1.4552x over previous
#include <cuda_runtime.h>
#include <cuda_bf16.h>
#include <stdint.h>

// Problem constants (match reference setup_inputs)
#define TOTAL   262144        // B*N = 16*16384
#define NGROUP  1024          // NUM_GROUPS
#define GSENT   1024          // sentinel group for masked-out nodes
#define NBLK    512           // number of stable-sort chunks
#define CHUNK   512           // TOTAL / NBLK
#define LOSS_THREADS 256
#define LOSS_BLOCKS  2048     // 16384 warps total
#define CHUNK_T      16       // sorted positions per warp

// ---------------- scratch (static __device__, no allocation) ----------------
__device__ int   d_geff[TOTAL];
__device__ int   d_rank[TOTAL];
__device__ int   d_histT[(NGROUP + 1) * NBLK];   // [g][b]
__device__ int   d_offT [(NGROUP + 1) * NBLK];   // [g][b] exclusive over b
__device__ int   d_counts[NGROUP + 1];
__device__ int   d_starts[NGROUP + 2];
__device__ int   d_order[TOTAL];
__device__ int   d_sortedG[TOTAL];
__device__ float d_partials[2 * LOSS_BLOCKS];
__device__ int   d_done;     // zero-initialized; last loss block resets to 0

// ---------------- threefry2x32 (JAX partitionable mode) ----------------
__device__ __forceinline__ unsigned rotl32(unsigned v, int d) {
    return (v << d) | (v >> (32 - d));
}

__device__ __forceinline__ void threefry2x32(unsigned k0, unsigned k1,
                                             unsigned& x0, unsigned& x1) {
    const unsigned ks0 = k0, ks1 = k1, ks2 = k0 ^ k1 ^ 0x1BD11BDAu;
    x0 += ks0; x1 += ks1;
#define TF_R4(a,b,c,d)                                  \
    x0 += x1; x1 = rotl32(x1, a); x1 ^= x0;             \
    x0 += x1; x1 = rotl32(x1, b); x1 ^= x0;             \
    x0 += x1; x1 = rotl32(x1, c); x1 ^= x0;             \
    x0 += x1; x1 = rotl32(x1, d); x1 ^= x0;
    TF_R4(13,15,26, 6); x0 += ks1; x1 += ks2 + 1u;
    TF_R4(17,29,16,24); x0 += ks2; x1 += ks0 + 2u;
    TF_R4(13,15,26, 6); x0 += ks0; x1 += ks1 + 3u;
    TF_R4(17,29,16,24); x0 += ks1; x1 += ks2 + 4u;
    TF_R4(13,15,26, 6); x0 += ks2; x1 += ks0 + 5u;
#undef TF_R4
}

// u[t]: counter = 64-bit flat index -> (hi=0, lo=t); draw = fold(out0^out1).
__device__ __forceinline__ float jax_uniform_at(int t) {
    unsigned x0 = 0u;
    unsigned x1 = (unsigned)t;
    threefry2x32(0u, 42u, x0, x1);       // jax.random.key(42) -> (0, 42)
    const unsigned bits = x0 ^ x1;
    return __uint_as_float((bits >> 9) | 0x3f800000u) - 1.0f;
}

// negative sorted-position for sorted index t
__device__ __forceinline__ int neg_pos(int t, int st, int cnt, int valid_total) {
    const float u = jax_uniform_at(t);
    const int comp = max(valid_total - cnt, 1);
    int r = (int)(u * (float)comp);
    if (r > comp - 1) r = comp - 1;
    int np_ = (r < st) ? r : r + cnt;
    if (np_ < 0) np_ = 0;
    if (np_ > TOTAL - 1) np_ = TOTAL - 1;
    return np_;
}

// ---------------- K1: stable per-chunk rank + per-chunk histogram ----------------
__global__ void rank_kernel(const int* __restrict__ groups,
                            const int* __restrict__ mask) {
    __shared__ int bins[NGROUP + 1];
    const int b = blockIdx.x;
    const int lane = threadIdx.x;
    for (int i = lane; i <= NGROUP; i += 32) bins[i] = 0;
    __syncwarp();
    const int base = b * CHUNK;
    for (int j = 0; j < CHUNK; j += 32) {
        const int i = base + j + lane;
        const int g = mask[i] ? groups[i] : GSENT;
        const unsigned m = __match_any_sync(0xffffffffu, g);
        const int rankInWarp = __popc(m & ((1u << lane) - 1u));
        const int leader = __ffs(m) - 1;
        int baseBin = 0;
        if (lane == leader) baseBin = atomicAdd(&bins[g], __popc(m));
        baseBin = __shfl_sync(0xffffffffu, baseBin, leader);
        d_rank[i] = baseBin + rankInWarp;
        d_geff[i] = g;
        __syncwarp();
    }
    for (int i = lane; i <= NGROUP; i += 32) d_histT[i * NBLK + b] = bins[i];
}

// ---------------- K2: per-group scan over chunks (one WARP per group) ----------
__global__ void colscan_kernel() {
    const int warpsPerBlock = blockDim.x >> 5;
    const int g = blockIdx.x * warpsPerBlock + (threadIdx.x >> 5);
    if (g > NGROUP) return;
    const int lane = threadIdx.x & 31;
    const int baseIdx = g * NBLK;
    int cum = 0;
    #pragma unroll
    for (int b0 = 0; b0 < NBLK; b0 += 32) {
        const int h = d_histT[baseIdx + b0 + lane];     // coalesced 128B
        int x = h;
        #pragma unroll
        for (int o = 1; o < 32; o <<= 1) {
            const int y = __shfl_up_sync(0xffffffffu, x, o);
            if (lane >= o) x += y;
        }
        d_offT[baseIdx + b0 + lane] = cum + x - h;      // exclusive
        cum += __shfl_sync(0xffffffffu, x, 31);
    }
    if (lane == 0) d_counts[g] = cum;
}

// ---------------- K3: exclusive scan of counts[0..1023] -> starts ----------------
__global__ void starts_kernel() {
    __shared__ int warpTot[32];
    const int t = threadIdx.x;               // blockDim = 1024
    const int lane = t & 31;
    const int w = t >> 5;
    const int v = d_counts[t];
    int x = v;
    #pragma unroll
    for (int o = 1; o < 32; o <<= 1) {
        const int y = __shfl_up_sync(0xffffffffu, x, o);
        if (lane >= o) x += y;
    }
    if (lane == 31) warpTot[w] = x;
    __syncthreads();
    if (w == 0) {
        int wt = warpTot[lane];
        #pragma unroll
        for (int o = 1; o < 32; o <<= 1) {
            const int y = __shfl_up_sync(0xffffffffu, wt, o);
            if (lane >= o) wt += y;
        }
        warpTot[lane] = wt;
    }
    __syncthreads();
    const int base = (w > 0) ? warpTot[w - 1] : 0;
    d_starts[t] = base + x - v;                           // exclusive
    if (t == 1023) d_starts[NGROUP] = base + x;           // = valid_total
}

// ---------------- K4: stable scatter ----------------
__global__ void scatter_kernel() {
    const int i = blockIdx.x * blockDim.x + threadIdx.x;
    if (i >= TOTAL) return;
    const int g = d_geff[i];
    const int b = i / CHUNK;
    const int pos = d_starts[g] + d_offT[g * NBLK + b] + d_rank[i];
    d_order[pos] = i;
    d_sortedG[pos] = g;
}

// ---------------- K5: main loss ----------------
// Lanes 0..15 precompute all indices/RNG for the warp's 16 sorted positions in
// parallel; the main loop (unroll-4) only streams embedding rows. Positives are
// register-carried (roll-by-1 identity) except at group starts.
__global__ void __launch_bounds__(LOSS_THREADS)
loss_kernel(const float4* __restrict__ emb, float* __restrict__ out) {
    const int lane = threadIdx.x & 31;
    const int warpInBlock = threadIdx.x >> 5;
    const int wid = blockIdx.x * (LOSS_THREADS / 32) + warpInBlock;
    const int lo = wid * CHUNK_T;
    const int valid_total = d_starts[NGROUP];

    // ---- per-lane precompute (lanes 0..15) ----
    int anchor = 0, negi = 0, posi = 0, isStart = 0, validL = 0, cntL = 0;
    if (lane < CHUNK_T) {
        const int t = lo + lane;
        const int g = __ldg(d_sortedG + t);
        anchor = __ldg(d_order + t);
        const int st = d_starts[g];
        const int cnt = d_counts[g];
        cntL = cnt;
        const int np = neg_pos(t, st, cnt, valid_total);
        negi = __ldg(d_order + np);
        isStart = (t == st);
        const int pIdx = isStart ? (st + cnt - 1) : (t - 1);
        posi = __ldg(d_order + pIdx);
        validL = (g < NGROUP) && (cnt >= 2) && ((valid_total - cnt) > 0);
    }

    float lsum = 0.0f, wsum = 0.0f;
    float4 aPrev = make_float4(0.f, 0.f, 0.f, 0.f);

    #pragma unroll 1
    for (int tp = 0; tp < CHUNK_T; tp += 4) {
        const unsigned FULL = 0xffffffffu;
        const int a0 = __shfl_sync(FULL, anchor, tp + 0);
        const int a1 = __shfl_sync(FULL, anchor, tp + 1);
        const int a2 = __shfl_sync(FULL, anchor, tp + 2);
        const int a3 = __shfl_sync(FULL, anchor, tp + 3);
        const int q0 = __shfl_sync(FULL, negi, tp + 0);
        const int q1 = __shfl_sync(FULL, negi, tp + 1);
        const int q2 = __shfl_sync(FULL, negi, tp + 2);
        const int q3 = __shfl_sync(FULL, negi, tp + 3);
        const int s0 = __shfl_sync(FULL, isStart, tp + 0);
        const int s1 = __shfl_sync(FULL, isStart, tp + 1);
        const int s2 = __shfl_sync(FULL, isStart, tp + 2);
        const int s3 = __shfl_sync(FULL, isStart, tp + 3);

        const float4 A0 = __ldg(&emb[a0 * 32 + lane]);
        const float4 A1 = __ldg(&emb[a1 * 32 + lane]);
        const float4 A2 = __ldg(&emb[a2 * 32 + lane]);
        const float4 A3 = __ldg(&emb[a3 * 32 + lane]);
        const float4 Q0 = __ldg(&emb[q0 * 32 + lane]);
        const float4 Q1 = __ldg(&emb[q1 * 32 + lane]);
        const float4 Q2 = __ldg(&emb[q2 * 32 + lane]);
        const float4 Q3 = __ldg(&emb[q3 * 32 + lane]);

        float4 P0;
        if (tp == 0 || s0) P0 = __ldg(&emb[__shfl_sync(FULL, posi, tp + 0) * 32 + lane]);
        else               P0 = aPrev;
        float4 P1 = s1 ? __ldg(&emb[__shfl_sync(FULL, posi, tp + 1) * 32 + lane]) : A0;
        float4 P2 = s2 ? __ldg(&emb[__shfl_sync(FULL, posi, tp + 2) * 32 + lane]) : A1;
        float4 P3 = s3 ? __ldg(&emb[__shfl_sync(FULL, posi, tp + 3) * 32 + lane]) : A2;
        aPrev = A3;

        float dp0 = A0.x*P0.x + A0.y*P0.y + A0.z*P0.z + A0.w*P0.w;
        float dn0 = A0.x*Q0.x + A0.y*Q0.y + A0.z*Q0.z + A0.w*Q0.w;
        float dp1 = A1.x*P1.x + A1.y*P1.y + A1.z*P1.z + A1.w*P1.w;
        float dn1 = A1.x*Q1.x + A1.y*Q1.y + A1.z*Q1.z + A1.w*Q1.w;
        float dp2 = A2.x*P2.x + A2.y*P2.y + A2.z*P2.z + A2.w*P2.w;
        float dn2 = A2.x*Q2.x + A2.y*Q2.y + A2.z*Q2.z + A2.w*Q2.w;
        float dp3 = A3.x*P3.x + A3.y*P3.y + A3.z*P3.z + A3.w*P3.w;
        float dn3 = A3.x*Q3.x + A3.y*Q3.y + A3.z*Q3.z + A3.w*Q3.w;
        #pragma unroll
        for (int o = 16; o; o >>= 1) {
            dp0 += __shfl_xor_sync(FULL, dp0, o);
            dn0 += __shfl_xor_sync(FULL, dn0, o);
            dp1 += __shfl_xor_sync(FULL, dp1, o);
            dn1 += __shfl_xor_sync(FULL, dn1, o);
            dp2 += __shfl_xor_sync(FULL, dp2, o);
            dn2 += __shfl_xor_sync(FULL, dn2, o);
            dp3 += __shfl_xor_sync(FULL, dp3, o);
            dn3 += __shfl_xor_sync(FULL, dn3, o);
        }

        // lanes 0..3 finish their own t in parallel (MUFU parallel, no serial lane0)
        const int vv = __shfl_sync(FULL, validL, tp + (lane & 3));
        if (lane < 4 && vv) {
            float dd;
            if      (lane == 0) dd = dn0 - dp0;
            else if (lane == 1) dd = dn1 - dp1;
            else if (lane == 2) dd = dn2 - dp2;
            else                dd = dn3 - dp3;
            dd *= 10.0f;                         // / TEMPERATURE
            lsum += fmaxf(dd, 0.0f) + log1pf(expf(-fabsf(dd)));
            wsum += 1.0f;
        }
    }

    // warp-reduce the lane-distributed sums
    #pragma unroll
    for (int o = 16; o; o >>= 1) {
        lsum += __shfl_xor_sync(0xffffffffu, lsum, o);
        wsum += __shfl_xor_sync(0xffffffffu, wsum, o);
    }

    // deterministic block reduction
    __shared__ float sl[LOSS_THREADS / 32];
    __shared__ float sw[LOSS_THREADS / 32];
    __shared__ int isLast;
    if (lane == 0) { sl[warpInBlock] = lsum; sw[warpInBlock] = wsum; }
    __syncthreads();
    if (threadIdx.x == 0) {
        float L = 0.0f, W = 0.0f;
        #pragma unroll
        for (int i = 0; i < LOSS_THREADS / 32; i++) { L += sl[i]; W += sw[i]; }
        d_partials[2 * blockIdx.x]     = L;
        d_partials[2 * blockIdx.x + 1] = W;
        __threadfence();
        isLast = (atomicAdd(&d_done, 1) == LOSS_BLOCKS - 1);
    }
    __syncthreads();

    // last finishing block does the deterministic final reduction
    if (isLast) {
        __shared__ float fl[256];
        __shared__ float fw[256];
        float L = 0.0f, W = 0.0f;
        for (int i = threadIdx.x; i < LOSS_BLOCKS; i += 256) {
            L += d_partials[2 * i];
            W += d_partials[2 * i + 1];
        }
        fl[threadIdx.x] = L; fw[threadIdx.x] = W;
        __syncthreads();
        for (int s = 128; s > 0; s >>= 1) {
            if (threadIdx.x < s) {
                fl[threadIdx.x] += fl[threadIdx.x + s];
                fw[threadIdx.x] += fw[threadIdx.x + s];
            }
            __syncthreads();
        }
        if (threadIdx.x == 0) {
            out[0] = fl[0] / fmaxf(fw[0], 1.0f);
            d_done = 0;                       // reset for graph replay
        }
    }
}

// ---------------- launch ----------------
extern "C" void kernel_launch(void* const* d_in, const int* in_sizes, int n_in,
                              void* d_out, int out_size) {
    const float4* emb   = (const float4*)d_in[0];
    const int*    grp   = (const int*)d_in[1];
    const int*    mask  = (const int*)d_in[2];
    float*        out   = (float*)d_out;
    (void)in_sizes; (void)n_in; (void)out_size;

    rank_kernel<<<NBLK, 32>>>(grp, mask);
    colscan_kernel<<<(NGROUP + 1 + 7) / 8, 256>>>();
    starts_kernel<<<1, 1024>>>();
    scatter_kernel<<<TOTAL / 256, 256>>>();
    loss_kernel<<<LOSS_BLOCKS, LOSS_THREADS>>>(emb, out);
}